// round 8
// baseline (speedup 1.0000x reference)
#include <cuda_runtime.h>
#include <cuda_bf16.h>
#include <cstdint>
#include <math.h>

// ---------------------------------------------------------------------------
// Problem constants
// ---------------------------------------------------------------------------
#define B_  8
#define L_  2048
#define C_  512
#define CI_ 256
#define MT_ 16384   // B_*L_

typedef __nv_bfloat16 bf16;

// ---------------------------------------------------------------------------
// Scratch (__device__ globals; allocation-free)
// ---------------------------------------------------------------------------
__device__ bf16  g_inH [(size_t)MT_ * C_];           // inputs hi  [bl][c]
__device__ bf16  g_inL [(size_t)MT_ * C_];           // inputs lo
__device__ bf16  g_xyH [(size_t)MT_ * C_];           // [x_proj | y_proj] hi [bl][512]
__device__ bf16  g_xyL [(size_t)MT_ * C_];
__device__ bf16  g_otH [(size_t)C_ * MT_];           // o_proj^T hi [c][bl]
__device__ bf16  g_otL [(size_t)C_ * MT_];
__device__ float g_scores[(size_t)B_ * L_ * L_];     // f32 logits
__device__ bf16  g_atH [(size_t)B_ * L_ * L_];       // attn hi [b][l][m]
__device__ bf16  g_atL [(size_t)B_ * L_ * L_];
__device__ bf16  g_wxyH[C_ * C_], g_wxyL[C_ * C_];   // [WxT ; WyT], [n][c]
__device__ bf16  g_wotH[C_ * C_], g_wotL[C_ * C_];   // WoT [d][c]
__device__ float g_bxy[C_];                          // concat(bx, by)
__device__ float g_bo [C_];                          // bo copy

// ---------------------------------------------------------------------------
// helpers
// ---------------------------------------------------------------------------
__device__ __forceinline__ uint32_t smem_u32(const void* p) {
    uint32_t a;
    asm("{ .reg .u64 t; cvta.to.shared.u64 t, %1; cvt.u32.u64 %0, t; }"
        : "=r"(a) : "l"(p));
    return a;
}
__device__ __forceinline__ void splitf(float v, bf16& h, bf16& l) {
    h = __float2bfloat16_rn(v);
    l = __float2bfloat16_rn(v - __bfloat162float(h));
}
__device__ __forceinline__ uint32_t pack2(bf16 a, bf16 b) {
    return (uint32_t)__bfloat16_as_ushort(a) |
           ((uint32_t)__bfloat16_as_ushort(b) << 16);
}

#define CP16(dst, src) \
    asm volatile("cp.async.ca.shared.global [%0], [%1], 16;" :: "r"(dst), "l"(src) : "memory")
#define CP_COMMIT() asm volatile("cp.async.commit_group;" ::: "memory")
#define CP_WAIT(n)  asm volatile("cp.async.wait_group %0;" :: "n"(n) : "memory")

#define LDSM_X4(r, a) \
    asm volatile("ldmatrix.sync.aligned.m8n8.x4.shared.b16 {%0,%1,%2,%3}, [%4];" \
        : "=r"((r)[0]), "=r"((r)[1]), "=r"((r)[2]), "=r"((r)[3]) : "r"(a))

__device__ __forceinline__ void mma_bf16(float* d, const uint32_t* a, const uint32_t* b) {
    asm volatile(
        "mma.sync.aligned.m16n8k16.row.col.f32.bf16.bf16.f32 "
        "{%0,%1,%2,%3}, {%4,%5,%6,%7}, {%8,%9}, {%0,%1,%2,%3};"
        : "+f"(d[0]), "+f"(d[1]), "+f"(d[2]), "+f"(d[3])
        : "r"(a[0]), "r"(a[1]), "r"(a[2]), "r"(a[3]), "r"(b[0]), "r"(b[1]));
}

// ---------------------------------------------------------------------------
// SMEM layout (128x128 tile, K-chunk 32, 80B rows, 2 stages) — 4 warps/CTA,
// warp tile 64x64 (2x2 warp grid): A re-read x2, B re-read x2 (was x2/x4).
// ---------------------------------------------------------------------------
#define ROWB   80u
#define TILE_B 10240u
#define STAGE_B 40960u
#define SMEM_GEMM_TOTAL (2 * 40960)
#define NTHREADS 128

__device__ __forceinline__ void stage_copy(
    uint32_t stage,
    const bf16* __restrict__ AH, const bf16* __restrict__ AL, int ldA, int m0,
    const bf16* __restrict__ BH, const bf16* __restrict__ BL, int ldB, int n0,
    int k0, int tid)
{
    #pragma unroll
    for (int t = 0; t < 4; ++t) {
        const bf16* base = (t == 0) ? AH : (t == 1) ? AL : (t == 2) ? BH : BL;
        const int ld = (t < 2) ? ldA : ldB;
        const int r0 = (t < 2) ? m0  : n0;
        #pragma unroll
        for (int j = 0; j < 4; ++j) {
            const int seg = tid + NTHREADS * j;   // 0..511
            const int r = seg >> 2, c = seg & 3;  // row 0..127, 16B chunk 0..3
            const bf16* src = base + (size_t)(r0 + r) * ld + k0 + c * 8;
            const uint32_t dst = stage + t * TILE_B + r * ROWB + c * 16u;
            CP16(dst, src);
        }
    }
}

// Main loop: fills acc (64x64 warp tile) from (AH+AL)(BH+BL)^T, 3-term bf16
template<int KTOT>
__device__ __forceinline__ void gemm_core(
    float acc[4][8][4],
    const bf16* __restrict__ aH, const bf16* __restrict__ aL, int ldA, int m0,
    const bf16* __restrict__ bH, const bf16* __restrict__ bL, int ldB, int n0,
    uint32_t smem_base, int tid, uint32_t aoff, uint32_t boff)
{
    constexpr int NC = KTOT / 32;

    stage_copy(smem_base, aH, aL, ldA, m0, bH, bL, ldB, n0, 0, tid);
    CP_COMMIT();
    if (NC > 1) {
        stage_copy(smem_base + STAGE_B, aH, aL, ldA, m0, bH, bL, ldB, n0, 32, tid);
        CP_COMMIT();
    }

    for (int kc = 0; kc < NC; ++kc) {
        if (kc + 1 < NC) { CP_WAIT(1); } else { CP_WAIT(0); }
        __syncthreads();

        const uint32_t stage = smem_base + (uint32_t)(kc & 1) * STAGE_B;
        #pragma unroll
        for (int ks = 0; ks < 2; ++ks) {
            uint32_t ah[4][4], al[4][4];
            #pragma unroll
            for (int mi = 0; mi < 4; ++mi) {
                LDSM_X4(ah[mi], stage + aoff + mi * 1280u + ks * 32u);
                LDSM_X4(al[mi], stage + TILE_B + aoff + mi * 1280u + ks * 32u);
            }
            #pragma unroll
            for (int h = 0; h < 2; ++h) {
                uint32_t bh2[8], bl2[8];
                #pragma unroll
                for (int q = 0; q < 2; ++q) {
                    LDSM_X4(bh2 + q * 4, stage + 2u * TILE_B + boff
                                         + (uint32_t)(h * 32 + q * 16) * ROWB + ks * 32u);
                    LDSM_X4(bl2 + q * 4, stage + 3u * TILE_B + boff
                                         + (uint32_t)(h * 32 + q * 16) * ROWB + ks * 32u);
                }
                #pragma unroll
                for (int njl = 0; njl < 4; ++njl) {
                    const int nj = h * 4 + njl;
                    const uint32_t* bhf = bh2 + njl * 2;
                    const uint32_t* blf = bl2 + njl * 2;
                    #pragma unroll
                    for (int mi = 0; mi < 4; ++mi) {
                        mma_bf16(acc[mi][nj], ah[mi], bhf);
                        mma_bf16(acc[mi][nj], ah[mi], blf);
                        mma_bf16(acc[mi][nj], al[mi], bhf);
                    }
                }
            }
        }

        if (kc + 2 < NC) {
            __syncthreads();
            stage_copy(stage, aH, aL, ldA, m0, bH, bL, ldB, n0, (kc + 2) * 32, tid);
            CP_COMMIT();
        }
    }
}

// ---------------------------------------------------------------------------
// Fused projection + o_proj^T kernel (both KTOT=512, bf16 HL outputs)
// z=0: xy = in @ Wxy^T + bxy[n]   grid (4=n, 128=m, .)
// z=1: ot = WoT @ in^T + bo[m]    grid (4=m, 128=n, .)
// ---------------------------------------------------------------------------
__global__ __launch_bounds__(NTHREADS, 2) void gemm_projot()
{
    extern __shared__ char smem[];
    const uint32_t smem_base = smem_u32(smem);

    const int tid  = threadIdx.x;
    const int wid  = tid >> 5;
    const int lane = tid & 31;
    const int g    = lane >> 2;
    const int t4   = lane & 3;
    const int wm   = (wid & 1) * 64;
    const int wn   = (wid >> 1) * 64;

    const int zz = blockIdx.z;
    const int m0 = (zz == 0) ? blockIdx.y * 128 : blockIdx.x * 128;
    const int n0 = (zz == 0) ? blockIdx.x * 128 : blockIdx.y * 128;

    const bf16* aH = (zz == 0) ? g_inH  : g_wotH;
    const bf16* aL = (zz == 0) ? g_inL  : g_wotL;
    const bf16* bH = (zz == 0) ? g_wxyH : g_inH;
    const bf16* bL = (zz == 0) ? g_wxyL : g_inL;

    const uint32_t aoff = (uint32_t)((wm + (lane & 7) + ((lane >> 3) & 1) * 8) * ROWB
                                     + (lane >> 4) * 16);
    const uint32_t boff = (uint32_t)((wn + (lane & 7) + ((lane >> 4) & 1) * 8) * ROWB
                                     + ((lane >> 3) & 1) * 16);

    float acc[4][8][4] = {};
    gemm_core<512>(acc, aH, aL, C_, m0, bH, bL, C_, n0, smem_base, tid, aoff, boff);

    bf16* CH  = (zz == 0) ? g_xyH : g_otH;
    bf16* CL  = (zz == 0) ? g_xyL : g_otL;
    const int ldC = (zz == 0) ? C_ : MT_;

    #pragma unroll
    for (int mi = 0; mi < 4; ++mi) {
        const int r0 = m0 + wm + mi * 16 + g;
        const int r1 = r0 + 8;
        const float bm0 = (zz == 1) ? g_bo[r0] : 0.f;
        const float bm1 = (zz == 1) ? g_bo[r1] : 0.f;
        #pragma unroll
        for (int nj = 0; nj < 8; ++nj) {
            const int col = n0 + wn + nj * 8 + 2 * t4;
            float2 v0 = make_float2(acc[mi][nj][0], acc[mi][nj][1]);
            float2 v1 = make_float2(acc[mi][nj][2], acc[mi][nj][3]);
            if (zz == 0) {
                const float2 bb = *(const float2*)&g_bxy[col];
                v0.x += bb.x; v0.y += bb.y; v1.x += bb.x; v1.y += bb.y;
            } else {
                v0.x += bm0; v0.y += bm0; v1.x += bm1; v1.y += bm1;
            }
            bf16 h0, l0, h1, l1;
            splitf(v0.x, h0, l0); splitf(v0.y, h1, l1);
            *(uint32_t*)&CH[(size_t)r0 * ldC + col] = pack2(h0, h1);
            *(uint32_t*)&CL[(size_t)r0 * ldC + col] = pack2(l0, l1);
            splitf(v1.x, h0, l0); splitf(v1.y, h1, l1);
            *(uint32_t*)&CH[(size_t)r1 * ldC + col] = pack2(h0, h1);
            *(uint32_t*)&CL[(size_t)r1 * ldC + col] = pack2(l0, l1);
        }
    }
}

// ---------------------------------------------------------------------------
// Batched GEMMs: scores (EPI 0, f32 out) and nn_out (EPI 3, +residual f32 out)
// ---------------------------------------------------------------------------
template<int KTOT, int EPI>
__global__ __launch_bounds__(NTHREADS, 2) void gemmHL(
    const bf16* __restrict__ AH, const bf16* __restrict__ AL, long long sA, int ldA,
    const bf16* __restrict__ BH, const bf16* __restrict__ BL, long long sB, int ldB,
    float* __restrict__ Cf, long long sC, int ldC,
    const float* __restrict__ aux, long long sAux)
{
    extern __shared__ char smem[];
    const uint32_t smem_base = smem_u32(smem);

    const int tid  = threadIdx.x;
    const int wid  = tid >> 5;
    const int lane = tid & 31;
    const int g    = lane >> 2;
    const int t4   = lane & 3;
    const int wm   = (wid & 1) * 64;
    const int wn   = (wid >> 1) * 64;

    const int bz = blockIdx.z;
    const int m0 = blockIdx.y * 128;
    const int n0 = blockIdx.x * 128;
    const bf16* aH = AH + (size_t)bz * sA;
    const bf16* aL = AL + (size_t)bz * sA;
    const bf16* bH = BH + (size_t)bz * sB;
    const bf16* bL = BL + (size_t)bz * sB;

    const uint32_t aoff = (uint32_t)((wm + (lane & 7) + ((lane >> 3) & 1) * 8) * ROWB
                                     + (lane >> 4) * 16);
    const uint32_t boff = (uint32_t)((wn + (lane & 7) + ((lane >> 4) & 1) * 8) * ROWB
                                     + ((lane >> 3) & 1) * 16);

    float acc[4][8][4] = {};
    gemm_core<KTOT>(acc, aH, aL, ldA, m0, bH, bL, ldB, n0, smem_base, tid, aoff, boff);

    const float* R = (EPI == 3) ? (aux + (size_t)bz * sAux) : nullptr;
    float* Cfb = Cf + (size_t)bz * sC;

    #pragma unroll
    for (int mi = 0; mi < 4; ++mi) {
        const int r0 = m0 + wm + mi * 16 + g;
        const int r1 = r0 + 8;
        #pragma unroll
        for (int nj = 0; nj < 8; ++nj) {
            const int col = n0 + wn + nj * 8 + 2 * t4;
            float2 v0 = make_float2(acc[mi][nj][0], acc[mi][nj][1]);
            float2 v1 = make_float2(acc[mi][nj][2], acc[mi][nj][3]);
            if (EPI == 3) {
                const float2 q0 = *(const float2*)&R[(size_t)r0 * ldC + col];
                const float2 q1 = *(const float2*)&R[(size_t)r1 * ldC + col];
                v0.x += q0.x; v0.y += q0.y; v1.x += q1.x; v1.y += q1.y;
            }
            *(float2*)&Cfb[(size_t)r0 * ldC + col] = v0;
            *(float2*)&Cfb[(size_t)r1 * ldC + col] = v1;
        }
    }
}

// ---------------------------------------------------------------------------
// Decompose inputs f32 -> bf16 hi/lo; first blocks also copy biases
// ---------------------------------------------------------------------------
__global__ __launch_bounds__(256) void decomp_inputs(
    const float* __restrict__ src, int n4,
    const float* __restrict__ bx, const float* __restrict__ by,
    const float* __restrict__ bo)
{
    const int i = blockIdx.x * 256 + threadIdx.x;
    if (i < C_) {
        g_bxy[i] = (i < CI_) ? bx[i] : by[i - CI_];
        g_bo[i]  = bo[i];
    }
    if (i >= n4) return;
    const float4 v = ((const float4*)src)[i];
    bf16 h0, h1, h2, h3, l0, l1, l2, l3;
    splitf(v.x, h0, l0); splitf(v.y, h1, l1);
    splitf(v.z, h2, l2); splitf(v.w, h3, l3);
    ((uint2*)g_inH)[i] = make_uint2(pack2(h0, h1), pack2(h2, h3));
    ((uint2*)g_inL)[i] = make_uint2(pack2(l0, l1), pack2(l2, l3));
}

// ---------------------------------------------------------------------------
// Single prep kernel: z selects Wx / Wy / Wo transpose+decompose
// ---------------------------------------------------------------------------
__global__ void prep_weights(const float* __restrict__ Wx,
                             const float* __restrict__ Wy,
                             const float* __restrict__ Wo)
{
    __shared__ float tbuf[32][33];
    const int zz = blockIdx.z;
    const int Cc = (zz == 2) ? C_ : CI_;
    if (blockIdx.x * 32 >= Cc) return;
    const float* src = (zz == 0) ? Wx : (zz == 1) ? Wy : Wo;
    bf16* H = (zz == 0) ? g_wxyH : (zz == 1) ? g_wxyH + (size_t)CI_ * C_ : g_wotH;
    bf16* L = (zz == 0) ? g_wxyL : (zz == 1) ? g_wxyL + (size_t)CI_ * C_ : g_wotL;

    const int bx = blockIdx.x * 32;
    const int by = blockIdx.y * 32;
    const int x = threadIdx.x, y = threadIdx.y;   // 32 x 8
    #pragma unroll
    for (int d = 0; d < 32; d += 8)
        tbuf[y + d][x] = src[(size_t)(by + y + d) * Cc + bx + x];
    __syncthreads();
    #pragma unroll
    for (int d = 0; d < 32; d += 8) {
        bf16 h, l;
        splitf(tbuf[x][y + d], h, l);
        H[(size_t)(bx + y + d) * C_ + by + x] = h;
        L[(size_t)(bx + y + d) * C_ + by + x] = l;
    }
}

// ---------------------------------------------------------------------------
// Softmax over batch axis, f32 logits -> bf16 hi/lo attn (float4 vectorized)
// ---------------------------------------------------------------------------
__global__ __launch_bounds__(256) void softmax_batch_HL()
{
    const size_t idx = ((size_t)blockIdx.x * 256 + threadIdx.x) * 4;
    const size_t stride = (size_t)L_ * L_;
    float4 v[B_];
    float4 mx = make_float4(-INFINITY, -INFINITY, -INFINITY, -INFINITY);
    #pragma unroll
    for (int b = 0; b < B_; ++b) {
        v[b] = *(const float4*)&g_scores[b * stride + idx];
        mx.x = fmaxf(mx.x, v[b].x); mx.y = fmaxf(mx.y, v[b].y);
        mx.z = fmaxf(mx.z, v[b].z); mx.w = fmaxf(mx.w, v[b].w);
    }
    float4 s = make_float4(0.f, 0.f, 0.f, 0.f);
    #pragma unroll
    for (int b = 0; b < B_; ++b) {
        v[b].x = __expf(v[b].x - mx.x); s.x += v[b].x;
        v[b].y = __expf(v[b].y - mx.y); s.y += v[b].y;
        v[b].z = __expf(v[b].z - mx.z); s.z += v[b].z;
        v[b].w = __expf(v[b].w - mx.w); s.w += v[b].w;
    }
    const float4 inv = make_float4(1.f / s.x, 1.f / s.y, 1.f / s.z, 1.f / s.w);
    #pragma unroll
    for (int b = 0; b < B_; ++b) {
        bf16 h0, l0, h1, l1, h2, l2, h3, l3;
        splitf(v[b].x * inv.x, h0, l0);
        splitf(v[b].y * inv.y, h1, l1);
        splitf(v[b].z * inv.z, h2, l2);
        splitf(v[b].w * inv.w, h3, l3);
        *(uint2*)&g_atH[b * stride + idx] = make_uint2(pack2(h0, h1), pack2(h2, h3));
        *(uint2*)&g_atL[b * stride + idx] = make_uint2(pack2(l0, l1), pack2(l2, l3));
    }
}

// ---------------------------------------------------------------------------
// Launch: inputs, Wx, bx, Wy, by, Wo, bo
// ---------------------------------------------------------------------------
extern "C" void kernel_launch(void* const* d_in, const int* in_sizes, int n_in,
                              void* d_out, int out_size)
{
    const float* inputs = (const float*)d_in[0];
    const float* Wx = (const float*)d_in[1];
    const float* bx = (const float*)d_in[2];
    const float* Wy = (const float*)d_in[3];
    const float* by = (const float*)d_in[4];
    const float* Wo = (const float*)d_in[5];
    const float* bo = (const float*)d_in[6];
    float* out = (float*)d_out;

    void *a;
    bf16 *xyH, *xyL, *otH, *otL, *atH, *atL;
    float *sc;
    cudaGetSymbolAddress(&a, g_xyH);  xyH  = (bf16*)a;
    cudaGetSymbolAddress(&a, g_xyL);  xyL  = (bf16*)a;
    cudaGetSymbolAddress(&a, g_otH);  otH  = (bf16*)a;
    cudaGetSymbolAddress(&a, g_otL);  otL  = (bf16*)a;
    cudaGetSymbolAddress(&a, g_atH);  atH  = (bf16*)a;
    cudaGetSymbolAddress(&a, g_atL);  atL  = (bf16*)a;
    cudaGetSymbolAddress(&a, g_scores); sc = (float*)a;

    cudaFuncSetAttribute((const void*)gemm_projot,
                         cudaFuncAttributeMaxDynamicSharedMemorySize, SMEM_GEMM_TOTAL);
    cudaFuncSetAttribute((const void*)gemmHL<256, 0>,
                         cudaFuncAttributeMaxDynamicSharedMemorySize, SMEM_GEMM_TOTAL);
    cudaFuncSetAttribute((const void*)gemmHL<2048, 3>,
                         cudaFuncAttributeMaxDynamicSharedMemorySize, SMEM_GEMM_TOTAL);

    // 0) decompose inputs (+bias copies), prep weights
    decomp_inputs<<<(MT_ * C_ / 4 + 255) / 256, 256>>>(inputs, MT_ * C_ / 4, bx, by, bo);
    prep_weights<<<dim3(16, 16, 3), dim3(32, 8)>>>(Wx, Wy, Wo);

    // 1) fused projection + o_proj^T (1024 CTAs, one tail)
    gemm_projot<<<dim3(4, 128, 2), NTHREADS, SMEM_GEMM_TOTAL>>>();

    // 2) scores[b] = x_proj[b] @ y_proj[b]^T
    gemmHL<256, 0><<<dim3(L_ / 128, L_ / 128, B_), NTHREADS, SMEM_GEMM_TOTAL>>>(
        xyH, xyL, (long long)L_ * C_, C_,
        xyH + CI_, xyL + CI_, (long long)L_ * C_, C_,
        sc, (long long)L_ * L_, L_, nullptr, 0);

    // 3) softmax over batch -> attn HL
    softmax_batch_HL<<<(L_ * L_ / 4) / 256, 256>>>();

    // 4) out[b] = inputs[b] + attn[b] @ o_proj[b]
    gemmHL<2048, 3><<<dim3(C_ / 128, L_ / 128, B_), NTHREADS, SMEM_GEMM_TOTAL>>>(
        atH, atL, (long long)L_ * L_, L_, otH, otL, (long long)L_, MT_,
        out, (long long)L_ * C_, C_, inputs, (long long)L_ * C_);
}

// round 9
// speedup vs baseline: 1.0552x; 1.0552x over previous
#include <cuda_runtime.h>
#include <cuda_bf16.h>
#include <cstdint>
#include <math.h>

// ---------------------------------------------------------------------------
// Problem constants
// ---------------------------------------------------------------------------
#define B_  8
#define L_  2048
#define C_  512
#define CI_ 256
#define MT_ 16384   // B_*L_

typedef __nv_bfloat16 bf16;

// ---------------------------------------------------------------------------
// Scratch (__device__ globals; allocation-free)
// ---------------------------------------------------------------------------
__device__ bf16  g_inH [(size_t)MT_ * C_];           // inputs hi  [bl][c]
__device__ bf16  g_inL [(size_t)MT_ * C_];           // inputs lo
__device__ bf16  g_xyH [(size_t)MT_ * C_];           // [x_proj | y_proj] hi [bl][512]
__device__ bf16  g_xyL [(size_t)MT_ * C_];
__device__ bf16  g_otH [(size_t)C_ * MT_];           // o_proj^T hi [c][bl]
__device__ bf16  g_otL [(size_t)C_ * MT_];
__device__ float g_scores[(size_t)B_ * L_ * L_];     // f32 logits
__device__ bf16  g_atH [(size_t)B_ * L_ * L_];       // attn hi [b][l][m]
__device__ bf16  g_atL [(size_t)B_ * L_ * L_];
__device__ bf16  g_wxyH[C_ * C_], g_wxyL[C_ * C_];   // [WxT ; WyT], [n][c]
__device__ bf16  g_wotH[C_ * C_], g_wotL[C_ * C_];   // WoT [d][c]
__device__ float g_bxy[C_];                          // concat(bx, by)
__device__ float g_bo [C_];                          // bo copy

// ---------------------------------------------------------------------------
// helpers
// ---------------------------------------------------------------------------
__device__ __forceinline__ uint32_t smem_u32(const void* p) {
    uint32_t a;
    asm("{ .reg .u64 t; cvta.to.shared.u64 t, %1; cvt.u32.u64 %0, t; }"
        : "=r"(a) : "l"(p));
    return a;
}
__device__ __forceinline__ void splitf(float v, bf16& h, bf16& l) {
    h = __float2bfloat16_rn(v);
    l = __float2bfloat16_rn(v - __bfloat162float(h));
}
__device__ __forceinline__ uint32_t pack2(bf16 a, bf16 b) {
    return (uint32_t)__bfloat16_as_ushort(a) |
           ((uint32_t)__bfloat16_as_ushort(b) << 16);
}

#define CP16(dst, src) \
    asm volatile("cp.async.ca.shared.global [%0], [%1], 16;" :: "r"(dst), "l"(src) : "memory")
#define CP_COMMIT() asm volatile("cp.async.commit_group;" ::: "memory")
#define CP_WAIT(n)  asm volatile("cp.async.wait_group %0;" :: "n"(n) : "memory")

#define LDSM_X4(r, a) \
    asm volatile("ldmatrix.sync.aligned.m8n8.x4.shared.b16 {%0,%1,%2,%3}, [%4];" \
        : "=r"((r)[0]), "=r"((r)[1]), "=r"((r)[2]), "=r"((r)[3]) : "r"(a))

__device__ __forceinline__ void mma_bf16(float* d, const uint32_t* a, const uint32_t* b) {
    asm volatile(
        "mma.sync.aligned.m16n8k16.row.col.f32.bf16.bf16.f32 "
        "{%0,%1,%2,%3}, {%4,%5,%6,%7}, {%8,%9}, {%0,%1,%2,%3};"
        : "+f"(d[0]), "+f"(d[1]), "+f"(d[2]), "+f"(d[3])
        : "r"(a[0]), "r"(a[1]), "r"(a[2]), "r"(a[3]), "r"(b[0]), "r"(b[1]));
}

// ---------------------------------------------------------------------------
// SMEM layout: 128x128 CTA tile, K-chunk 32, 64B rows with XOR swizzle
// (chunk ^= (row>>1)&3) -> conflict-free ldmatrix, no padding.
// 4 tiles x 8192 B = 32768 B/stage, 3 stages = 98304 B. 2 CTAs/SM.
// 8 warps (4M x 2N), warp tile 32x64 (the proven R7 geometry).
// Single __syncthreads per chunk (3-stage ring makes WAR safe).
// ---------------------------------------------------------------------------
#define ROWB    64u
#define TILE_B  8192u
#define STAGE_B 32768u
#define NSTAGE  3
#define SMEM_GEMM_TOTAL (NSTAGE * 32768)
#define NTHREADS 256

__device__ __forceinline__ void stage_copy(
    uint32_t stage,
    const bf16* __restrict__ AH, const bf16* __restrict__ AL, int ldA, int m0,
    const bf16* __restrict__ BH, const bf16* __restrict__ BL, int ldB, int n0,
    int k0, int tid)
{
    #pragma unroll
    for (int t = 0; t < 4; ++t) {
        const bf16* base = (t == 0) ? AH : (t == 1) ? AL : (t == 2) ? BH : BL;
        const int ld = (t < 2) ? ldA : ldB;
        const int r0 = (t < 2) ? m0  : n0;
        #pragma unroll
        for (int j = 0; j < 2; ++j) {
            const int seg = tid + NTHREADS * j;   // 0..511
            const int r = seg >> 2, c = seg & 3;  // row 0..127, 16B chunk 0..3
            const int csw = c ^ ((r >> 1) & 3);   // XOR swizzle
            const bf16* src = base + (size_t)(r0 + r) * ld + k0 + c * 8;
            const uint32_t dst = stage + t * TILE_B + r * ROWB + csw * 16u;
            CP16(dst, src);
        }
    }
}

// Main loop: fills acc (32x64 warp tile) from (AH+AL)(BH+BL)^T, 3-term bf16
template<int KTOT>
__device__ __forceinline__ void gemm_core(
    float acc[2][8][4],
    const bf16* __restrict__ aH, const bf16* __restrict__ aL, int ldA, int m0,
    const bf16* __restrict__ bH, const bf16* __restrict__ bL, int ldB, int n0,
    uint32_t smem_base, int tid, int wm, int wn, int lane)
{
    constexpr int NC = KTOT / 32;

    // per-lane swizzle key and row-base byte offsets
    const uint32_t key  = (uint32_t)(((lane & 7) >> 1) & 3);
    const uint32_t aRow = (uint32_t)(wm + (lane & 7) + ((lane >> 3) & 1) * 8) * ROWB;
    const uint32_t bRow = (uint32_t)(wn + (lane & 7) + ((lane >> 4) & 1) * 8) * ROWB;
    const uint32_t aCh  = (uint32_t)(lane >> 4);        // nominal 16B chunk (A)
    const uint32_t bCh  = (uint32_t)((lane >> 3) & 1);  // nominal 16B chunk (B)

    stage_copy(smem_base, aH, aL, ldA, m0, bH, bL, ldB, n0, 0, tid);
    CP_COMMIT();
    stage_copy(smem_base + STAGE_B, aH, aL, ldA, m0, bH, bL, ldB, n0, 32, tid);
    CP_COMMIT();

    uint32_t stage = smem_base;   // stage for kc (cycles through 3)
    for (int kc = 0; kc < NC; ++kc) {
        if (kc + 1 < NC) { CP_WAIT(1); } else { CP_WAIT(0); }
        __syncthreads();

        #pragma unroll
        for (int ks = 0; ks < 2; ++ks) {
            uint32_t ah[2][4], al[2][4];
            const uint32_t aSw = ((uint32_t)(ks * 2) + aCh) ^ key;
            const uint32_t bSw = ((uint32_t)(ks * 2) + bCh) ^ key;
            #pragma unroll
            for (int mi = 0; mi < 2; ++mi) {
                const uint32_t base = stage + aRow + mi * (16u * ROWB) + aSw * 16u;
                LDSM_X4(ah[mi], base);
                LDSM_X4(al[mi], base + TILE_B);
            }
            #pragma unroll
            for (int h = 0; h < 2; ++h) {
                uint32_t bh2[8], bl2[8];
                #pragma unroll
                for (int q = 0; q < 2; ++q) {
                    const uint32_t base = stage + 2u * TILE_B + bRow
                                        + (uint32_t)(h * 32 + q * 16) * ROWB + bSw * 16u;
                    LDSM_X4(bh2 + q * 4, base);
                    LDSM_X4(bl2 + q * 4, base + TILE_B);
                }
                #pragma unroll
                for (int njl = 0; njl < 4; ++njl) {
                    const int nj = h * 4 + njl;
                    const uint32_t* bhf = bh2 + njl * 2;
                    const uint32_t* blf = bl2 + njl * 2;
                    #pragma unroll
                    for (int mi = 0; mi < 2; ++mi) {
                        mma_bf16(acc[mi][nj], ah[mi], bhf);
                        mma_bf16(acc[mi][nj], ah[mi], blf);
                        mma_bf16(acc[mi][nj], al[mi], bhf);
                    }
                }
            }
        }

        // prefetch chunk kc+2 into the stage freed at kc-1 (safe: one sync/chunk)
        if (kc + 2 < NC) {
            uint32_t wstage = stage + 2 * STAGE_B;
            if (wstage >= smem_base + NSTAGE * STAGE_B) wstage -= NSTAGE * STAGE_B;
            stage_copy(wstage, aH, aL, ldA, m0, bH, bL, ldB, n0, (kc + 2) * 32, tid);
            CP_COMMIT();
        }
        stage += STAGE_B;
        if (stage >= smem_base + NSTAGE * STAGE_B) stage = smem_base;
    }
}

// ---------------------------------------------------------------------------
// Fused projection + o_proj^T kernel (both KTOT=512, bf16 HL outputs)
// z=0: xy = in @ Wxy^T + bxy[n]   grid (4=n, 128=m, .)
// z=1: ot = WoT @ in^T + bo[m]    grid (4=m, 128=n, .)
// ---------------------------------------------------------------------------
__global__ __launch_bounds__(NTHREADS, 2) void gemm_projot()
{
    extern __shared__ char smem[];
    const uint32_t smem_base = smem_u32(smem);

    const int tid  = threadIdx.x;
    const int wid  = tid >> 5;
    const int lane = tid & 31;
    const int g    = lane >> 2;
    const int t4   = lane & 3;
    const int wm   = (wid & 3) * 32;
    const int wn   = (wid >> 2) * 64;

    const int zz = blockIdx.z;
    const int m0 = (zz == 0) ? blockIdx.y * 128 : blockIdx.x * 128;
    const int n0 = (zz == 0) ? blockIdx.x * 128 : blockIdx.y * 128;

    const bf16* aH = (zz == 0) ? g_inH  : g_wotH;
    const bf16* aL = (zz == 0) ? g_inL  : g_wotL;
    const bf16* bH = (zz == 0) ? g_wxyH : g_inH;
    const bf16* bL = (zz == 0) ? g_wxyL : g_inL;

    float acc[2][8][4] = {};
    gemm_core<512>(acc, aH, aL, C_, m0, bH, bL, C_, n0, smem_base, tid, wm, wn, lane);

    bf16* CH  = (zz == 0) ? g_xyH : g_otH;
    bf16* CL  = (zz == 0) ? g_xyL : g_otL;
    const int ldC = (zz == 0) ? C_ : MT_;

    #pragma unroll
    for (int mi = 0; mi < 2; ++mi) {
        const int r0 = m0 + wm + mi * 16 + g;
        const int r1 = r0 + 8;
        const float bm0 = (zz == 1) ? g_bo[r0] : 0.f;
        const float bm1 = (zz == 1) ? g_bo[r1] : 0.f;
        #pragma unroll
        for (int nj = 0; nj < 8; ++nj) {
            const int col = n0 + wn + nj * 8 + 2 * t4;
            float2 v0 = make_float2(acc[mi][nj][0], acc[mi][nj][1]);
            float2 v1 = make_float2(acc[mi][nj][2], acc[mi][nj][3]);
            if (zz == 0) {
                const float2 bb = *(const float2*)&g_bxy[col];
                v0.x += bb.x; v0.y += bb.y; v1.x += bb.x; v1.y += bb.y;
            } else {
                v0.x += bm0; v0.y += bm0; v1.x += bm1; v1.y += bm1;
            }
            bf16 h0, l0, h1, l1;
            splitf(v0.x, h0, l0); splitf(v0.y, h1, l1);
            *(uint32_t*)&CH[(size_t)r0 * ldC + col] = pack2(h0, h1);
            *(uint32_t*)&CL[(size_t)r0 * ldC + col] = pack2(l0, l1);
            splitf(v1.x, h0, l0); splitf(v1.y, h1, l1);
            *(uint32_t*)&CH[(size_t)r1 * ldC + col] = pack2(h0, h1);
            *(uint32_t*)&CL[(size_t)r1 * ldC + col] = pack2(l0, l1);
        }
    }
}

// ---------------------------------------------------------------------------
// Batched GEMMs: scores (EPI 0, f32 out) and nn_out (EPI 3, +residual f32 out)
// ---------------------------------------------------------------------------
template<int KTOT, int EPI>
__global__ __launch_bounds__(NTHREADS, 2) void gemmHL(
    const bf16* __restrict__ AH, const bf16* __restrict__ AL, long long sA, int ldA,
    const bf16* __restrict__ BH, const bf16* __restrict__ BL, long long sB, int ldB,
    float* __restrict__ Cf, long long sC, int ldC,
    const float* __restrict__ aux, long long sAux)
{
    extern __shared__ char smem[];
    const uint32_t smem_base = smem_u32(smem);

    const int tid  = threadIdx.x;
    const int wid  = tid >> 5;
    const int lane = tid & 31;
    const int g    = lane >> 2;
    const int t4   = lane & 3;
    const int wm   = (wid & 3) * 32;
    const int wn   = (wid >> 2) * 64;

    const int bz = blockIdx.z;
    const int m0 = blockIdx.y * 128;
    const int n0 = blockIdx.x * 128;
    const bf16* aH = AH + (size_t)bz * sA;
    const bf16* aL = AL + (size_t)bz * sA;
    const bf16* bH = BH + (size_t)bz * sB;
    const bf16* bL = BL + (size_t)bz * sB;

    float acc[2][8][4] = {};
    gemm_core<KTOT>(acc, aH, aL, ldA, m0, bH, bL, ldB, n0, smem_base, tid, wm, wn, lane);

    const float* R = (EPI == 3) ? (aux + (size_t)bz * sAux) : nullptr;
    float* Cfb = Cf + (size_t)bz * sC;

    #pragma unroll
    for (int mi = 0; mi < 2; ++mi) {
        const int r0 = m0 + wm + mi * 16 + g;
        const int r1 = r0 + 8;
        #pragma unroll
        for (int nj = 0; nj < 8; ++nj) {
            const int col = n0 + wn + nj * 8 + 2 * t4;
            float2 v0 = make_float2(acc[mi][nj][0], acc[mi][nj][1]);
            float2 v1 = make_float2(acc[mi][nj][2], acc[mi][nj][3]);
            if (EPI == 3) {
                const float2 q0 = *(const float2*)&R[(size_t)r0 * ldC + col];
                const float2 q1 = *(const float2*)&R[(size_t)r1 * ldC + col];
                v0.x += q0.x; v0.y += q0.y; v1.x += q1.x; v1.y += q1.y;
            }
            *(float2*)&Cfb[(size_t)r0 * ldC + col] = v0;
            *(float2*)&Cfb[(size_t)r1 * ldC + col] = v1;
        }
    }
}

// ---------------------------------------------------------------------------
// Decompose inputs f32 -> bf16 hi/lo; first blocks also copy biases
// ---------------------------------------------------------------------------
__global__ __launch_bounds__(256) void decomp_inputs(
    const float* __restrict__ src, int n4,
    const float* __restrict__ bx, const float* __restrict__ by,
    const float* __restrict__ bo)
{
    const int i = blockIdx.x * 256 + threadIdx.x;
    if (i < C_) {
        g_bxy[i] = (i < CI_) ? bx[i] : by[i - CI_];
        g_bo[i]  = bo[i];
    }
    if (i >= n4) return;
    const float4 v = ((const float4*)src)[i];
    bf16 h0, h1, h2, h3, l0, l1, l2, l3;
    splitf(v.x, h0, l0); splitf(v.y, h1, l1);
    splitf(v.z, h2, l2); splitf(v.w, h3, l3);
    ((uint2*)g_inH)[i] = make_uint2(pack2(h0, h1), pack2(h2, h3));
    ((uint2*)g_inL)[i] = make_uint2(pack2(l0, l1), pack2(l2, l3));
}

// ---------------------------------------------------------------------------
// Single prep kernel: z selects Wx / Wy / Wo transpose+decompose
// ---------------------------------------------------------------------------
__global__ void prep_weights(const float* __restrict__ Wx,
                             const float* __restrict__ Wy,
                             const float* __restrict__ Wo)
{
    __shared__ float tbuf[32][33];
    const int zz = blockIdx.z;
    const int Cc = (zz == 2) ? C_ : CI_;
    if (blockIdx.x * 32 >= Cc) return;
    const float* src = (zz == 0) ? Wx : (zz == 1) ? Wy : Wo;
    bf16* H = (zz == 0) ? g_wxyH : (zz == 1) ? g_wxyH + (size_t)CI_ * C_ : g_wotH;
    bf16* L = (zz == 0) ? g_wxyL : (zz == 1) ? g_wxyL + (size_t)CI_ * C_ : g_wotL;

    const int bx = blockIdx.x * 32;
    const int by = blockIdx.y * 32;
    const int x = threadIdx.x, y = threadIdx.y;   // 32 x 8
    #pragma unroll
    for (int d = 0; d < 32; d += 8)
        tbuf[y + d][x] = src[(size_t)(by + y + d) * Cc + bx + x];
    __syncthreads();
    #pragma unroll
    for (int d = 0; d < 32; d += 8) {
        bf16 h, l;
        splitf(tbuf[x][y + d], h, l);
        H[(size_t)(bx + y + d) * C_ + by + x] = h;
        L[(size_t)(bx + y + d) * C_ + by + x] = l;
    }
}

// ---------------------------------------------------------------------------
// Softmax over batch axis, f32 logits -> bf16 hi/lo attn (float4 vectorized)
// ---------------------------------------------------------------------------
__global__ __launch_bounds__(256) void softmax_batch_HL()
{
    const size_t idx = ((size_t)blockIdx.x * 256 + threadIdx.x) * 4;
    const size_t stride = (size_t)L_ * L_;
    float4 v[B_];
    float4 mx = make_float4(-INFINITY, -INFINITY, -INFINITY, -INFINITY);
    #pragma unroll
    for (int b = 0; b < B_; ++b) {
        v[b] = *(const float4*)&g_scores[b * stride + idx];
        mx.x = fmaxf(mx.x, v[b].x); mx.y = fmaxf(mx.y, v[b].y);
        mx.z = fmaxf(mx.z, v[b].z); mx.w = fmaxf(mx.w, v[b].w);
    }
    float4 s = make_float4(0.f, 0.f, 0.f, 0.f);
    #pragma unroll
    for (int b = 0; b < B_; ++b) {
        v[b].x = __expf(v[b].x - mx.x); s.x += v[b].x;
        v[b].y = __expf(v[b].y - mx.y); s.y += v[b].y;
        v[b].z = __expf(v[b].z - mx.z); s.z += v[b].z;
        v[b].w = __expf(v[b].w - mx.w); s.w += v[b].w;
    }
    const float4 inv = make_float4(1.f / s.x, 1.f / s.y, 1.f / s.z, 1.f / s.w);
    #pragma unroll
    for (int b = 0; b < B_; ++b) {
        bf16 h0, l0, h1, l1, h2, l2, h3, l3;
        splitf(v[b].x * inv.x, h0, l0);
        splitf(v[b].y * inv.y, h1, l1);
        splitf(v[b].z * inv.z, h2, l2);
        splitf(v[b].w * inv.w, h3, l3);
        *(uint2*)&g_atH[b * stride + idx] = make_uint2(pack2(h0, h1), pack2(h2, h3));
        *(uint2*)&g_atL[b * stride + idx] = make_uint2(pack2(l0, l1), pack2(l2, l3));
    }
}

// ---------------------------------------------------------------------------
// Launch: inputs, Wx, bx, Wy, by, Wo, bo
// ---------------------------------------------------------------------------
extern "C" void kernel_launch(void* const* d_in, const int* in_sizes, int n_in,
                              void* d_out, int out_size)
{
    const float* inputs = (const float*)d_in[0];
    const float* Wx = (const float*)d_in[1];
    const float* bx = (const float*)d_in[2];
    const float* Wy = (const float*)d_in[3];
    const float* by = (const float*)d_in[4];
    const float* Wo = (const float*)d_in[5];
    const float* bo = (const float*)d_in[6];
    float* out = (float*)d_out;

    void *a;
    bf16 *xyH, *xyL, *otH, *otL, *atH, *atL;
    float *sc;
    cudaGetSymbolAddress(&a, g_xyH);  xyH  = (bf16*)a;
    cudaGetSymbolAddress(&a, g_xyL);  xyL  = (bf16*)a;
    cudaGetSymbolAddress(&a, g_otH);  otH  = (bf16*)a;
    cudaGetSymbolAddress(&a, g_otL);  otL  = (bf16*)a;
    cudaGetSymbolAddress(&a, g_atH);  atH  = (bf16*)a;
    cudaGetSymbolAddress(&a, g_atL);  atL  = (bf16*)a;
    cudaGetSymbolAddress(&a, g_scores); sc = (float*)a;

    cudaFuncSetAttribute((const void*)gemm_projot,
                         cudaFuncAttributeMaxDynamicSharedMemorySize, SMEM_GEMM_TOTAL);
    cudaFuncSetAttribute((const void*)gemmHL<256, 0>,
                         cudaFuncAttributeMaxDynamicSharedMemorySize, SMEM_GEMM_TOTAL);
    cudaFuncSetAttribute((const void*)gemmHL<2048, 3>,
                         cudaFuncAttributeMaxDynamicSharedMemorySize, SMEM_GEMM_TOTAL);

    // 0) decompose inputs (+bias copies), prep weights
    decomp_inputs<<<(MT_ * C_ / 4 + 255) / 256, 256>>>(inputs, MT_ * C_ / 4, bx, by, bo);
    prep_weights<<<dim3(16, 16, 3), dim3(32, 8)>>>(Wx, Wy, Wo);

    // 1) fused projection + o_proj^T (1024 CTAs, one tail)
    gemm_projot<<<dim3(4, 128, 2), NTHREADS, SMEM_GEMM_TOTAL>>>();

    // 2) scores[b] = x_proj[b] @ y_proj[b]^T
    gemmHL<256, 0><<<dim3(L_ / 128, L_ / 128, B_), NTHREADS, SMEM_GEMM_TOTAL>>>(
        xyH, xyL, (long long)L_ * C_, C_,
        xyH + CI_, xyL + CI_, (long long)L_ * C_, C_,
        sc, (long long)L_ * L_, L_, nullptr, 0);

    // 3) softmax over batch -> attn HL
    softmax_batch_HL<<<(L_ * L_ / 4) / 256, 256>>>();

    // 4) out[b] = inputs[b] + attn[b] @ o_proj[b]
    gemmHL<2048, 3><<<dim3(C_ / 128, L_ / 128, B_), NTHREADS, SMEM_GEMM_TOTAL>>>(
        atH, atL, (long long)L_ * L_, L_, otH, otL, (long long)L_, MT_,
        out, (long long)L_ * C_, C_, inputs, (long long)L_ * C_);
}

// round 10
// speedup vs baseline: 1.0577x; 1.0024x over previous
#include <cuda_runtime.h>
#include <cuda_bf16.h>
#include <cstdint>
#include <math.h>

// ---------------------------------------------------------------------------
// Problem constants
// ---------------------------------------------------------------------------
#define B_  8
#define L_  2048
#define C_  512
#define CI_ 256
#define MT_ 16384   // B_*L_

typedef __nv_bfloat16 bf16;

// ---------------------------------------------------------------------------
// Scratch (__device__ globals; allocation-free)
// ---------------------------------------------------------------------------
__device__ bf16  g_inH [(size_t)MT_ * C_];           // inputs hi  [bl][c]
__device__ bf16  g_inL [(size_t)MT_ * C_];           // inputs lo
__device__ bf16  g_xyH [(size_t)MT_ * C_];           // [x_proj | y_proj] hi [bl][512]
__device__ bf16  g_xyL [(size_t)MT_ * C_];
__device__ bf16  g_otH [(size_t)C_ * MT_];           // o_proj^T hi [c][bl]
__device__ bf16  g_otL [(size_t)C_ * MT_];
__device__ float g_scores[(size_t)B_ * L_ * L_];     // f32 logits
__device__ bf16  g_atH [(size_t)B_ * L_ * L_];       // attn hi [b][l][m]
__device__ bf16  g_atL [(size_t)B_ * L_ * L_];
__device__ bf16  g_wxyH[C_ * C_], g_wxyL[C_ * C_];   // [WxT ; WyT], [n][c]
__device__ bf16  g_wotH[C_ * C_], g_wotL[C_ * C_];   // WoT [d][c]
__device__ float g_bxy[C_];                          // concat(bx, by)
__device__ float g_bo [C_];                          // bo copy

// ---------------------------------------------------------------------------
// helpers
// ---------------------------------------------------------------------------
__device__ __forceinline__ uint32_t smem_u32(const void* p) {
    uint32_t a;
    asm("{ .reg .u64 t; cvta.to.shared.u64 t, %1; cvt.u32.u64 %0, t; }"
        : "=r"(a) : "l"(p));
    return a;
}
__device__ __forceinline__ void splitf(float v, bf16& h, bf16& l) {
    h = __float2bfloat16_rn(v);
    l = __float2bfloat16_rn(v - __bfloat162float(h));
}
__device__ __forceinline__ uint32_t pack2(bf16 a, bf16 b) {
    return (uint32_t)__bfloat16_as_ushort(a) |
           ((uint32_t)__bfloat16_as_ushort(b) << 16);
}

#define CP16(dst, src) \
    asm volatile("cp.async.ca.shared.global [%0], [%1], 16;" :: "r"(dst), "l"(src) : "memory")
#define CP_COMMIT() asm volatile("cp.async.commit_group;" ::: "memory")
#define CP_WAIT(n)  asm volatile("cp.async.wait_group %0;" :: "n"(n) : "memory")

#define LDSM_X4(r, a) \
    asm volatile("ldmatrix.sync.aligned.m8n8.x4.shared.b16 {%0,%1,%2,%3}, [%4];" \
        : "=r"((r)[0]), "=r"((r)[1]), "=r"((r)[2]), "=r"((r)[3]) : "r"(a))

// NOTE: non-volatile — all effects are in register constraints; lets ptxas
// schedule MMAs to hide HMMA latency across independent accumulators.
__device__ __forceinline__ void mma_bf16(float* d, const uint32_t* a, const uint32_t* b) {
    asm("mma.sync.aligned.m16n8k16.row.col.f32.bf16.bf16.f32 "
        "{%0,%1,%2,%3}, {%4,%5,%6,%7}, {%8,%9}, {%0,%1,%2,%3};"
        : "+f"(d[0]), "+f"(d[1]), "+f"(d[2]), "+f"(d[3])
        : "r"(a[0]), "r"(a[1]), "r"(a[2]), "r"(a[3]), "r"(b[0]), "r"(b[1]));
}

// ---------------------------------------------------------------------------
// SMEM layout: 128x128 CTA tile, K-chunk 32, 64B rows with XOR swizzle
// (chunk ^= (row>>1)&3) -> conflict-free ldmatrix, no padding.
// 4 tiles x 8192 B = 32768 B/stage, 3 stages = 98304 B. 2 CTAs/SM.
// 8 warps (4M x 2N), warp tile 32x64. Single __syncthreads per chunk.
// MMAs issued term-major (hh pass, hl pass, lh pass) to kill acc RAW chains.
// ---------------------------------------------------------------------------
#define ROWB    64u
#define TILE_B  8192u
#define STAGE_B 32768u
#define NSTAGE  3
#define SMEM_GEMM_TOTAL (NSTAGE * 32768)
#define NTHREADS 256

__device__ __forceinline__ void stage_copy(
    uint32_t stage,
    const bf16* __restrict__ AH, const bf16* __restrict__ AL, int ldA, int m0,
    const bf16* __restrict__ BH, const bf16* __restrict__ BL, int ldB, int n0,
    int k0, int tid)
{
    #pragma unroll
    for (int t = 0; t < 4; ++t) {
        const bf16* base = (t == 0) ? AH : (t == 1) ? AL : (t == 2) ? BH : BL;
        const int ld = (t < 2) ? ldA : ldB;
        const int r0 = (t < 2) ? m0  : n0;
        #pragma unroll
        for (int j = 0; j < 2; ++j) {
            const int seg = tid + NTHREADS * j;   // 0..511
            const int r = seg >> 2, c = seg & 3;  // row 0..127, 16B chunk 0..3
            const int csw = c ^ ((r >> 1) & 3);   // XOR swizzle
            const bf16* src = base + (size_t)(r0 + r) * ld + k0 + c * 8;
            const uint32_t dst = stage + t * TILE_B + r * ROWB + csw * 16u;
            CP16(dst, src);
        }
    }
}

// Main loop: fills acc (32x64 warp tile) from (AH+AL)(BH+BL)^T, 3-term bf16
template<int KTOT>
__device__ __forceinline__ void gemm_core(
    float acc[2][8][4],
    const bf16* __restrict__ aH, const bf16* __restrict__ aL, int ldA, int m0,
    const bf16* __restrict__ bH, const bf16* __restrict__ bL, int ldB, int n0,
    uint32_t smem_base, int tid, int wm, int wn, int lane)
{
    constexpr int NC = KTOT / 32;

    // per-lane swizzle key and row-base byte offsets
    const uint32_t key  = (uint32_t)(((lane & 7) >> 1) & 3);
    const uint32_t aRow = (uint32_t)(wm + (lane & 7) + ((lane >> 3) & 1) * 8) * ROWB;
    const uint32_t bRow = (uint32_t)(wn + (lane & 7) + ((lane >> 4) & 1) * 8) * ROWB;
    const uint32_t aCh  = (uint32_t)(lane >> 4);        // nominal 16B chunk (A)
    const uint32_t bCh  = (uint32_t)((lane >> 3) & 1);  // nominal 16B chunk (B)

    stage_copy(smem_base, aH, aL, ldA, m0, bH, bL, ldB, n0, 0, tid);
    CP_COMMIT();
    stage_copy(smem_base + STAGE_B, aH, aL, ldA, m0, bH, bL, ldB, n0, 32, tid);
    CP_COMMIT();

    uint32_t stage = smem_base;   // stage for kc (cycles through 3)
    for (int kc = 0; kc < NC; ++kc) {
        if (kc + 1 < NC) { CP_WAIT(1); } else { CP_WAIT(0); }
        __syncthreads();

        #pragma unroll
        for (int ks = 0; ks < 2; ++ks) {
            uint32_t ah[2][4], al[2][4];
            const uint32_t aSw = ((uint32_t)(ks * 2) + aCh) ^ key;
            const uint32_t bSw = ((uint32_t)(ks * 2) + bCh) ^ key;
            #pragma unroll
            for (int mi = 0; mi < 2; ++mi) {
                const uint32_t base = stage + aRow + mi * (16u * ROWB) + aSw * 16u;
                LDSM_X4(ah[mi], base);
                LDSM_X4(al[mi], base + TILE_B);
            }
            #pragma unroll
            for (int h = 0; h < 2; ++h) {
                uint32_t bh2[8], bl2[8];
                #pragma unroll
                for (int q = 0; q < 2; ++q) {
                    const uint32_t base = stage + 2u * TILE_B + bRow
                                        + (uint32_t)(h * 32 + q * 16) * ROWB + bSw * 16u;
                    LDSM_X4(bh2 + q * 4, base);
                    LDSM_X4(bl2 + q * 4, base + TILE_B);
                }
                // term-major passes: consecutive MMAs hit distinct accumulators
                // (per-acc addition order hh -> hl -> lh preserved => bit-identical)
                #pragma unroll
                for (int njl = 0; njl < 4; ++njl) {
                    const int nj = h * 4 + njl;
                    #pragma unroll
                    for (int mi = 0; mi < 2; ++mi)
                        mma_bf16(acc[mi][nj], ah[mi], bh2 + njl * 2);
                }
                #pragma unroll
                for (int njl = 0; njl < 4; ++njl) {
                    const int nj = h * 4 + njl;
                    #pragma unroll
                    for (int mi = 0; mi < 2; ++mi)
                        mma_bf16(acc[mi][nj], ah[mi], bl2 + njl * 2);
                }
                #pragma unroll
                for (int njl = 0; njl < 4; ++njl) {
                    const int nj = h * 4 + njl;
                    #pragma unroll
                    for (int mi = 0; mi < 2; ++mi)
                        mma_bf16(acc[mi][nj], al[mi], bh2 + njl * 2);
                }
            }
        }

        // prefetch chunk kc+2 into the stage freed at kc-1 (safe: one sync/chunk)
        if (kc + 2 < NC) {
            uint32_t wstage = stage + 2 * STAGE_B;
            if (wstage >= smem_base + NSTAGE * STAGE_B) wstage -= NSTAGE * STAGE_B;
            stage_copy(wstage, aH, aL, ldA, m0, bH, bL, ldB, n0, (kc + 2) * 32, tid);
            CP_COMMIT();
        }
        stage += STAGE_B;
        if (stage >= smem_base + NSTAGE * STAGE_B) stage = smem_base;
    }
}

// ---------------------------------------------------------------------------
// Fused projection + o_proj^T kernel (both KTOT=512, bf16 HL outputs)
// z=0: xy = in @ Wxy^T + bxy[n]   grid (4=n, 128=m, .)
// z=1: ot = WoT @ in^T + bo[m]    grid (4=m, 128=n, .)
// ---------------------------------------------------------------------------
__global__ __launch_bounds__(NTHREADS, 2) void gemm_projot()
{
    extern __shared__ char smem[];
    const uint32_t smem_base = smem_u32(smem);

    const int tid  = threadIdx.x;
    const int wid  = tid >> 5;
    const int lane = tid & 31;
    const int g    = lane >> 2;
    const int t4   = lane & 3;
    const int wm   = (wid & 3) * 32;
    const int wn   = (wid >> 2) * 64;

    const int zz = blockIdx.z;
    const int m0 = (zz == 0) ? blockIdx.y * 128 : blockIdx.x * 128;
    const int n0 = (zz == 0) ? blockIdx.x * 128 : blockIdx.y * 128;

    const bf16* aH = (zz == 0) ? g_inH  : g_wotH;
    const bf16* aL = (zz == 0) ? g_inL  : g_wotL;
    const bf16* bH = (zz == 0) ? g_wxyH : g_inH;
    const bf16* bL = (zz == 0) ? g_wxyL : g_inL;

    float acc[2][8][4] = {};
    gemm_core<512>(acc, aH, aL, C_, m0, bH, bL, C_, n0, smem_base, tid, wm, wn, lane);

    bf16* CH  = (zz == 0) ? g_xyH : g_otH;
    bf16* CL  = (zz == 0) ? g_xyL : g_otL;
    const int ldC = (zz == 0) ? C_ : MT_;

    #pragma unroll
    for (int mi = 0; mi < 2; ++mi) {
        const int r0 = m0 + wm + mi * 16 + g;
        const int r1 = r0 + 8;
        const float bm0 = (zz == 1) ? g_bo[r0] : 0.f;
        const float bm1 = (zz == 1) ? g_bo[r1] : 0.f;
        #pragma unroll
        for (int nj = 0; nj < 8; ++nj) {
            const int col = n0 + wn + nj * 8 + 2 * t4;
            float2 v0 = make_float2(acc[mi][nj][0], acc[mi][nj][1]);
            float2 v1 = make_float2(acc[mi][nj][2], acc[mi][nj][3]);
            if (zz == 0) {
                const float2 bb = *(const float2*)&g_bxy[col];
                v0.x += bb.x; v0.y += bb.y; v1.x += bb.x; v1.y += bb.y;
            } else {
                v0.x += bm0; v0.y += bm0; v1.x += bm1; v1.y += bm1;
            }
            bf16 h0, l0, h1, l1;
            splitf(v0.x, h0, l0); splitf(v0.y, h1, l1);
            *(uint32_t*)&CH[(size_t)r0 * ldC + col] = pack2(h0, h1);
            *(uint32_t*)&CL[(size_t)r0 * ldC + col] = pack2(l0, l1);
            splitf(v1.x, h0, l0); splitf(v1.y, h1, l1);
            *(uint32_t*)&CH[(size_t)r1 * ldC + col] = pack2(h0, h1);
            *(uint32_t*)&CL[(size_t)r1 * ldC + col] = pack2(l0, l1);
        }
    }
}

// ---------------------------------------------------------------------------
// Batched GEMMs: scores (EPI 0, f32 out) and nn_out (EPI 3, +residual f32 out)
// ---------------------------------------------------------------------------
template<int KTOT, int EPI>
__global__ __launch_bounds__(NTHREADS, 2) void gemmHL(
    const bf16* __restrict__ AH, const bf16* __restrict__ AL, long long sA, int ldA,
    const bf16* __restrict__ BH, const bf16* __restrict__ BL, long long sB, int ldB,
    float* __restrict__ Cf, long long sC, int ldC,
    const float* __restrict__ aux, long long sAux)
{
    extern __shared__ char smem[];
    const uint32_t smem_base = smem_u32(smem);

    const int tid  = threadIdx.x;
    const int wid  = tid >> 5;
    const int lane = tid & 31;
    const int g    = lane >> 2;
    const int t4   = lane & 3;
    const int wm   = (wid & 3) * 32;
    const int wn   = (wid >> 2) * 64;

    const int bz = blockIdx.z;
    const int m0 = blockIdx.y * 128;
    const int n0 = blockIdx.x * 128;
    const bf16* aH = AH + (size_t)bz * sA;
    const bf16* aL = AL + (size_t)bz * sA;
    const bf16* bH = BH + (size_t)bz * sB;
    const bf16* bL = BL + (size_t)bz * sB;

    float acc[2][8][4] = {};
    gemm_core<KTOT>(acc, aH, aL, ldA, m0, bH, bL, ldB, n0, smem_base, tid, wm, wn, lane);

    const float* R = (EPI == 3) ? (aux + (size_t)bz * sAux) : nullptr;
    float* Cfb = Cf + (size_t)bz * sC;

    #pragma unroll
    for (int mi = 0; mi < 2; ++mi) {
        const int r0 = m0 + wm + mi * 16 + g;
        const int r1 = r0 + 8;
        #pragma unroll
        for (int nj = 0; nj < 8; ++nj) {
            const int col = n0 + wn + nj * 8 + 2 * t4;
            float2 v0 = make_float2(acc[mi][nj][0], acc[mi][nj][1]);
            float2 v1 = make_float2(acc[mi][nj][2], acc[mi][nj][3]);
            if (EPI == 3) {
                const float2 q0 = *(const float2*)&R[(size_t)r0 * ldC + col];
                const float2 q1 = *(const float2*)&R[(size_t)r1 * ldC + col];
                v0.x += q0.x; v0.y += q0.y; v1.x += q1.x; v1.y += q1.y;
            }
            *(float2*)&Cfb[(size_t)r0 * ldC + col] = v0;
            *(float2*)&Cfb[(size_t)r1 * ldC + col] = v1;
        }
    }
}

// ---------------------------------------------------------------------------
// Decompose inputs f32 -> bf16 hi/lo; first blocks also copy biases
// ---------------------------------------------------------------------------
__global__ __launch_bounds__(256) void decomp_inputs(
    const float* __restrict__ src, int n4,
    const float* __restrict__ bx, const float* __restrict__ by,
    const float* __restrict__ bo)
{
    const int i = blockIdx.x * 256 + threadIdx.x;
    if (i < C_) {
        g_bxy[i] = (i < CI_) ? bx[i] : by[i - CI_];
        g_bo[i]  = bo[i];
    }
    if (i >= n4) return;
    const float4 v = ((const float4*)src)[i];
    bf16 h0, h1, h2, h3, l0, l1, l2, l3;
    splitf(v.x, h0, l0); splitf(v.y, h1, l1);
    splitf(v.z, h2, l2); splitf(v.w, h3, l3);
    ((uint2*)g_inH)[i] = make_uint2(pack2(h0, h1), pack2(h2, h3));
    ((uint2*)g_inL)[i] = make_uint2(pack2(l0, l1), pack2(l2, l3));
}

// ---------------------------------------------------------------------------
// Single prep kernel: z selects Wx / Wy / Wo transpose+decompose
// ---------------------------------------------------------------------------
__global__ void prep_weights(const float* __restrict__ Wx,
                             const float* __restrict__ Wy,
                             const float* __restrict__ Wo)
{
    __shared__ float tbuf[32][33];
    const int zz = blockIdx.z;
    const int Cc = (zz == 2) ? C_ : CI_;
    if (blockIdx.x * 32 >= Cc) return;
    const float* src = (zz == 0) ? Wx : (zz == 1) ? Wy : Wo;
    bf16* H = (zz == 0) ? g_wxyH : (zz == 1) ? g_wxyH + (size_t)CI_ * C_ : g_wotH;
    bf16* L = (zz == 0) ? g_wxyL : (zz == 1) ? g_wxyL + (size_t)CI_ * C_ : g_wotL;

    const int bx = blockIdx.x * 32;
    const int by = blockIdx.y * 32;
    const int x = threadIdx.x, y = threadIdx.y;   // 32 x 8
    #pragma unroll
    for (int d = 0; d < 32; d += 8)
        tbuf[y + d][x] = src[(size_t)(by + y + d) * Cc + bx + x];
    __syncthreads();
    #pragma unroll
    for (int d = 0; d < 32; d += 8) {
        bf16 h, l;
        splitf(tbuf[x][y + d], h, l);
        H[(size_t)(bx + y + d) * C_ + by + x] = h;
        L[(size_t)(bx + y + d) * C_ + by + x] = l;
    }
}

// ---------------------------------------------------------------------------
// Softmax over batch axis, f32 logits -> bf16 hi/lo attn (float4 vectorized)
// ---------------------------------------------------------------------------
__global__ __launch_bounds__(256) void softmax_batch_HL()
{
    const size_t idx = ((size_t)blockIdx.x * 256 + threadIdx.x) * 4;
    const size_t stride = (size_t)L_ * L_;
    float4 v[B_];
    float4 mx = make_float4(-INFINITY, -INFINITY, -INFINITY, -INFINITY);
    #pragma unroll
    for (int b = 0; b < B_; ++b) {
        v[b] = *(const float4*)&g_scores[b * stride + idx];
        mx.x = fmaxf(mx.x, v[b].x); mx.y = fmaxf(mx.y, v[b].y);
        mx.z = fmaxf(mx.z, v[b].z); mx.w = fmaxf(mx.w, v[b].w);
    }
    float4 s = make_float4(0.f, 0.f, 0.f, 0.f);
    #pragma unroll
    for (int b = 0; b < B_; ++b) {
        v[b].x = __expf(v[b].x - mx.x); s.x += v[b].x;
        v[b].y = __expf(v[b].y - mx.y); s.y += v[b].y;
        v[b].z = __expf(v[b].z - mx.z); s.z += v[b].z;
        v[b].w = __expf(v[b].w - mx.w); s.w += v[b].w;
    }
    const float4 inv = make_float4(1.f / s.x, 1.f / s.y, 1.f / s.z, 1.f / s.w);
    #pragma unroll
    for (int b = 0; b < B_; ++b) {
        bf16 h0, l0, h1, l1, h2, l2, h3, l3;
        splitf(v[b].x * inv.x, h0, l0);
        splitf(v[b].y * inv.y, h1, l1);
        splitf(v[b].z * inv.z, h2, l2);
        splitf(v[b].w * inv.w, h3, l3);
        *(uint2*)&g_atH[b * stride + idx] = make_uint2(pack2(h0, h1), pack2(h2, h3));
        *(uint2*)&g_atL[b * stride + idx] = make_uint2(pack2(l0, l1), pack2(l2, l3));
    }
}

// ---------------------------------------------------------------------------
// Launch: inputs, Wx, bx, Wy, by, Wo, bo
// ---------------------------------------------------------------------------
extern "C" void kernel_launch(void* const* d_in, const int* in_sizes, int n_in,
                              void* d_out, int out_size)
{
    const float* inputs = (const float*)d_in[0];
    const float* Wx = (const float*)d_in[1];
    const float* bx = (const float*)d_in[2];
    const float* Wy = (const float*)d_in[3];
    const float* by = (const float*)d_in[4];
    const float* Wo = (const float*)d_in[5];
    const float* bo = (const float*)d_in[6];
    float* out = (float*)d_out;

    void *a;
    bf16 *xyH, *xyL, *otH, *otL, *atH, *atL;
    float *sc;
    cudaGetSymbolAddress(&a, g_xyH);  xyH  = (bf16*)a;
    cudaGetSymbolAddress(&a, g_xyL);  xyL  = (bf16*)a;
    cudaGetSymbolAddress(&a, g_otH);  otH  = (bf16*)a;
    cudaGetSymbolAddress(&a, g_otL);  otL  = (bf16*)a;
    cudaGetSymbolAddress(&a, g_atH);  atH  = (bf16*)a;
    cudaGetSymbolAddress(&a, g_atL);  atL  = (bf16*)a;
    cudaGetSymbolAddress(&a, g_scores); sc = (float*)a;

    cudaFuncSetAttribute((const void*)gemm_projot,
                         cudaFuncAttributeMaxDynamicSharedMemorySize, SMEM_GEMM_TOTAL);
    cudaFuncSetAttribute((const void*)gemmHL<256, 0>,
                         cudaFuncAttributeMaxDynamicSharedMemorySize, SMEM_GEMM_TOTAL);
    cudaFuncSetAttribute((const void*)gemmHL<2048, 3>,
                         cudaFuncAttributeMaxDynamicSharedMemorySize, SMEM_GEMM_TOTAL);

    // 0) decompose inputs (+bias copies), prep weights
    decomp_inputs<<<(MT_ * C_ / 4 + 255) / 256, 256>>>(inputs, MT_ * C_ / 4, bx, by, bo);
    prep_weights<<<dim3(16, 16, 3), dim3(32, 8)>>>(Wx, Wy, Wo);

    // 1) fused projection + o_proj^T (1024 CTAs, one tail)
    gemm_projot<<<dim3(4, 128, 2), NTHREADS, SMEM_GEMM_TOTAL>>>();

    // 2) scores[b] = x_proj[b] @ y_proj[b]^T
    gemmHL<256, 0><<<dim3(L_ / 128, L_ / 128, B_), NTHREADS, SMEM_GEMM_TOTAL>>>(
        xyH, xyL, (long long)L_ * C_, C_,
        xyH + CI_, xyL + CI_, (long long)L_ * C_, C_,
        sc, (long long)L_ * L_, L_, nullptr, 0);

    // 3) softmax over batch -> attn HL
    softmax_batch_HL<<<(L_ * L_ / 4) / 256, 256>>>();

    // 4) out[b] = inputs[b] + attn[b] @ o_proj[b]
    gemmHL<2048, 3><<<dim3(C_ / 128, L_ / 128, B_), NTHREADS, SMEM_GEMM_TOTAL>>>(
        atH, atL, (long long)L_ * L_, L_, otH, otL, (long long)L_, MT_,
        out, (long long)L_ * C_, C_, inputs, (long long)L_ * C_);
}